// round 3
// baseline (speedup 1.0000x reference)
#include <cuda_runtime.h>

#define NN   524288      // nodes
#define NE   12582912    // edges
#define NB   64          // graphs
#define NPER 8192        // nodes per graph
#define F0   8
#define HID  5

// ---------------- device scratch (static; no allocation allowed) ----------------
// 16B record: ea(float4) with the 19-bit src index packed into mantissa LSBs
// (5 bits in x, 5 in y, 5 in z, 4 in w). Perturbs ea by <= 2^-18 relative.
__device__ uint4  g_rec[NE];           // 201 MB CSR records
__device__ float  g_xn[NN * F0];       // normalized x
__device__ float  g_h1[NN * HID];      // layer-1 output
__device__ float  g_h2[NN * HID];      // layer-2 output
__device__ float  g_xl[NN * 8];        // padded to 32B rows (one sector per gather)
__device__ float  g_xr[NN * 8];
__device__ int    g_cnt[NN];
__device__ int    g_rowptr[NN + 1];
__device__ int    g_fill[NN];
__device__ unsigned long long g_scanstate[512];
__device__ int    g_ticket;            // scan block ordering
__device__ int    g_ticket2;           // scatter completion counter
__device__ double g_easum[4];
__device__ float4 g_eamean;

// ---------------- GraphNorm + zero + layer-1 lr, fused (one block per graph) ----------------
__global__ void k_gn(const float* __restrict__ x, const float* __restrict__ w,
                     const float* __restrict__ b, const float* __restrict__ ms,
                     const float* __restrict__ Wl, const float* __restrict__ bl,
                     const float* __restrict__ Wr, const float* __restrict__ br) {
    int g = blockIdx.x, tid = threadIdx.x;

    // per-launch state zeroing (grid-stride over all blocks)
    for (int i = g * 256 + tid; i < NN; i += NB * 256) g_cnt[i] = 0;
    if (g == 0) {
        if (tid < 4) g_easum[tid] = 0.0;
        if (tid == 4) g_ticket = 0;
        if (tid == 5) g_ticket2 = 0;
        for (int i = tid; i < 512; i += 256) g_scanstate[i] = 0ULL;
    }

    __shared__ float sWl[40], sWr[40], sbl[5], sbr[5];
    if (tid < 40) { sWl[tid] = Wl[tid]; sWr[tid] = Wr[tid]; }
    if (tid >= 40 && tid < 45) { sbl[tid - 40] = bl[tid - 40]; sbr[tid - 40] = br[tid - 40]; }

    float s1[F0], s2[F0];
#pragma unroll
    for (int f = 0; f < F0; f++) { s1[f] = 0.f; s2[f] = 0.f; }
    for (int r = tid; r < NPER; r += blockDim.x) {
        const float* row = x + (size_t)(g * NPER + r) * F0;
#pragma unroll
        for (int f = 0; f < F0; f++) { float v = row[f]; s1[f] += v; s2[f] += v * v; }
    }
#pragma unroll
    for (int off = 16; off > 0; off >>= 1)
#pragma unroll
        for (int f = 0; f < F0; f++) {
            s1[f] += __shfl_xor_sync(0xffffffffu, s1[f], off);
            s2[f] += __shfl_xor_sync(0xffffffffu, s2[f], off);
        }
    __shared__ float sm[8][2 * F0];
    int wp = tid >> 5, lane = tid & 31;
    if (lane == 0) {
#pragma unroll
        for (int f = 0; f < F0; f++) { sm[wp][f] = s1[f]; sm[wp][F0 + f] = s2[f]; }
    }
    __syncthreads();
    __shared__ float meanms[F0], scale[F0], bias[F0];
    if (tid < F0) {
        float t1 = 0.f, t2 = 0.f;
        for (int k = 0; k < 8; k++) { t1 += sm[k][tid]; t2 += sm[k][F0 + tid]; }
        float mean = t1 / (float)NPER, ex2 = t2 / (float)NPER, m = ms[tid];
        float var = ex2 - 2.f * m * mean * mean + m * m * mean * mean;
        meanms[tid] = m * mean;
        scale[tid] = w[tid] * rsqrtf(var + 1e-5f);
        bias[tid] = b[tid];
    }
    __syncthreads();
    for (int r = tid; r < NPER; r += blockDim.x) {
        int n = g * NPER + r;
        const float* row = x + (size_t)n * F0;
        float xv[F0];
        float* orow = g_xn + (size_t)n * F0;
#pragma unroll
        for (int f = 0; f < F0; f++) {
            xv[f] = scale[f] * (row[f] - meanms[f]) + bias[f];
            orow[f] = xv[f];
        }
        // fused layer-1 xl/xr transforms
        float l[5], rr[5];
#pragma unroll
        for (int j = 0; j < 5; j++) { l[j] = sbl[j]; rr[j] = sbr[j]; }
#pragma unroll
        for (int i = 0; i < F0; i++)
#pragma unroll
            for (int j = 0; j < 5; j++) {
                l[j] = fmaf(xv[i], sWl[i * 5 + j], l[j]);
                rr[j] = fmaf(xv[i], sWr[i * 5 + j], rr[j]);
            }
        float4* lp = (float4*)(g_xl + n * 8);
        float4* rp = (float4*)(g_xr + n * 8);
        lp[0] = make_float4(l[0], l[1], l[2], l[3]);
        lp[1] = make_float4(l[4], 0.f, 0.f, 0.f);
        rp[0] = make_float4(rr[0], rr[1], rr[2], rr[3]);
        rp[1] = make_float4(rr[4], 0.f, 0.f, 0.f);
    }
}

// ---------------- degree count ----------------
__global__ void k_count(const int* __restrict__ dst) {
    int stride = gridDim.x * blockDim.x;
    const int4* d4 = (const int4*)dst;
    for (int e = blockIdx.x * blockDim.x + threadIdx.x; e < NE / 4; e += stride) {
        int4 d = __ldcs(d4 + e);
        atomicAdd(&g_cnt[d.x], 1);
        atomicAdd(&g_cnt[d.y], 1);
        atomicAdd(&g_cnt[d.z], 1);
        atomicAdd(&g_cnt[d.w], 1);
    }
}

// ---------------- single-pass decoupled-lookback scan ----------------
__global__ __launch_bounds__(1024) void k_scan() {
    __shared__ int s[1024];
    __shared__ int sbid;
    __shared__ int sexc;
    int tid = threadIdx.x;
    if (tid == 0) { sbid = atomicAdd(&g_ticket, 1); sexc = 0; }
    __syncthreads();
    int bid = sbid;
    int idx = bid * 1024 + tid;
    int v = g_cnt[idx];
    s[tid] = v;
    __syncthreads();
    for (int off = 1; off < 1024; off <<= 1) {
        int t = (tid >= off) ? s[tid - off] : 0;
        __syncthreads();
        s[tid] += t;
        __syncthreads();
    }
    int total = s[1023];
    if (tid == 0) {
        unsigned long long st = bid == 0 ? ((2ULL << 32) | (unsigned)total)
                                         : ((1ULL << 32) | (unsigned)total);
        atomicExch(&g_scanstate[bid], st);
    }
    __syncthreads();
    if (bid > 0 && tid < 32) {
        int exc = 0;
        int j = bid - 1;
        bool done = false;
        while (!done) {
            int widx = j - tid;
            unsigned long long t = (widx >= 0) ? atomicOr(&g_scanstate[widx], 0ULL)
                                               : (2ULL << 32);
            unsigned f = (unsigned)(t >> 32);
            int val = (int)(unsigned)t;
            unsigned bP = __ballot_sync(0xffffffffu, f == 2u);
            unsigned bI = __ballot_sync(0xffffffffu, f == 0u);
            int fP = bP ? (__ffs(bP) - 1) : 99;
            int fI = bI ? (__ffs(bI) - 1) : 99;
            if (fI < fP) continue;               // unknown block closer than a prefix: retry
            int contrib;
            if (fP < 99) { contrib = (tid <= fP) ? val : 0; done = true; }
            else         { contrib = val; j -= 32; }
#pragma unroll
            for (int o = 16; o > 0; o >>= 1)
                contrib += __shfl_xor_sync(0xffffffffu, contrib, o);
            exc += contrib;
        }
        if (tid == 0) {
            atomicExch(&g_scanstate[bid], (2ULL << 32) | (unsigned)(exc + total));
            sexc = exc;
        }
    }
    __syncthreads();
    int p = sexc + s[tid] - v;           // exclusive global prefix
    g_rowptr[idx] = p;
    g_fill[idx] = p;
    if (bid == 0 && tid == 0) g_rowptr[NN] = NE;
}

// ---------------- scatter into CSR records (+ edge-attr mean) ----------------
__device__ __forceinline__ uint4 pack_rec(float4 v, int s) {
    uint4 u;
    u.x = (__float_as_uint(v.x) & ~31u) | ((unsigned)s >> 14);
    u.y = (__float_as_uint(v.y) & ~31u) | (((unsigned)s >> 9) & 31u);
    u.z = (__float_as_uint(v.z) & ~31u) | (((unsigned)s >> 4) & 31u);
    u.w = (__float_as_uint(v.w) & ~15u) | ((unsigned)s & 15u);
    return u;
}

__global__ void k_scatter(const int* __restrict__ src, const int* __restrict__ dst,
                          const float* __restrict__ ea) {
    int stride = gridDim.x * blockDim.x;
    const int4* s4 = (const int4*)src;
    const int4* d4 = (const int4*)dst;
    const float4* e4 = (const float4*)ea;
    double a0 = 0.0, a1 = 0.0, a2 = 0.0, a3 = 0.0;
    for (int e = blockIdx.x * blockDim.x + threadIdx.x; e < NE / 4; e += stride) {
        int4 ss = __ldcs(s4 + e);
        int4 dd = __ldcs(d4 + e);
        float4 v0 = __ldcs(e4 + (size_t)e * 4 + 0);
        float4 v1 = __ldcs(e4 + (size_t)e * 4 + 1);
        float4 v2 = __ldcs(e4 + (size_t)e * 4 + 2);
        float4 v3 = __ldcs(e4 + (size_t)e * 4 + 3);
        a0 += (double)v0.x + v1.x + v2.x + v3.x;
        a1 += (double)v0.y + v1.y + v2.y + v3.y;
        a2 += (double)v0.z + v1.z + v2.z + v3.z;
        a3 += (double)v0.w + v1.w + v2.w + v3.w;
        __stcs(&g_rec[atomicAdd(&g_fill[dd.x], 1)], pack_rec(v0, ss.x));
        __stcs(&g_rec[atomicAdd(&g_fill[dd.y], 1)], pack_rec(v1, ss.y));
        __stcs(&g_rec[atomicAdd(&g_fill[dd.z], 1)], pack_rec(v2, ss.z));
        __stcs(&g_rec[atomicAdd(&g_fill[dd.w], 1)], pack_rec(v3, ss.w));
    }
#pragma unroll
    for (int off = 16; off > 0; off >>= 1) {
        a0 += __shfl_xor_sync(0xffffffffu, a0, off);
        a1 += __shfl_xor_sync(0xffffffffu, a1, off);
        a2 += __shfl_xor_sync(0xffffffffu, a2, off);
        a3 += __shfl_xor_sync(0xffffffffu, a3, off);
    }
    __shared__ double sd[8][4];
    int wp = threadIdx.x >> 5, lane = threadIdx.x & 31;
    if (lane == 0) { sd[wp][0] = a0; sd[wp][1] = a1; sd[wp][2] = a2; sd[wp][3] = a3; }
    __syncthreads();
    if (threadIdx.x < 4) {
        double t = 0.0;
        for (int k = 0; k < 8; k++) t += sd[k][threadIdx.x];
        atomicAdd(&g_easum[threadIdx.x], t);
    }
    __syncthreads();
    if (threadIdx.x == 0) {
        __threadfence();
        int t = atomicAdd(&g_ticket2, 1);
        if (t == (int)gridDim.x - 1) {       // last block: finalize edge-attr mean
            __threadfence();
            double inv = 1.0 / (double)NE;
            double e0 = *((volatile double*)&g_easum[0]);
            double e1 = *((volatile double*)&g_easum[1]);
            double e2 = *((volatile double*)&g_easum[2]);
            double e3 = *((volatile double*)&g_easum[3]);
            g_eamean = make_float4((float)(e0 * inv), (float)(e1 * inv),
                                   (float)(e2 * inv), (float)(e3 * inv));
        }
    }
}

// ---------------- layer-2 xl/xr transforms ----------------
__global__ void k_lr2(const float* __restrict__ Wl, const float* __restrict__ bl,
                      const float* __restrict__ Wr, const float* __restrict__ br) {
    int n = blockIdx.x * blockDim.x + threadIdx.x;
    if (n >= NN) return;
    float xv[13];
#pragma unroll
    for (int j = 0; j < 5; j++) xv[j] = g_h1[n * 5 + j];
#pragma unroll
    for (int f = 0; f < 8; f++) xv[5 + f] = g_xn[n * 8 + f];
    float l[5], r[5];
#pragma unroll
    for (int j = 0; j < 5; j++) { l[j] = bl[j]; r[j] = br[j]; }
#pragma unroll
    for (int i = 0; i < 13; i++)
#pragma unroll
        for (int j = 0; j < 5; j++) {
            l[j] = fmaf(xv[i], Wl[i * 5 + j], l[j]);
            r[j] = fmaf(xv[i], Wr[i * 5 + j], r[j]);
        }
    float4* lp = (float4*)(g_xl + n * 8);
    float4* rp = (float4*)(g_xr + n * 8);
    lp[0] = make_float4(l[0], l[1], l[2], l[3]);
    lp[1] = make_float4(l[4], 0.f, 0.f, 0.f);
    rp[0] = make_float4(r[0], r[1], r[2], r[3]);
    rp[1] = make_float4(r[4], 0.f, 0.f, 0.f);
}

// ---------------- GATv2 layer: one warp per node, plain-exp softmax ----------------
// softmax is shift-invariant; logits are O(+-25) here so exp() cannot overflow fp32.
template<int L>
__global__ void k_gat(const float* __restrict__ We, const float* __restrict__ att,
                      const float* __restrict__ bo) {
    const int lane = threadIdx.x & 31;
    const int node = blockIdx.x * (256 / 32) + (threadIdx.x >> 5);
    float* __restrict__ hout = (L == 1) ? g_h1 : g_h2;

    float we[4][5], av[5];
#pragma unroll
    for (int k = 0; k < 4; k++)
#pragma unroll
        for (int j = 0; j < 5; j++) we[k][j] = We[k * 5 + j];
#pragma unroll
    for (int j = 0; j < 5; j++) av[j] = att[j];

    float xrv[5], xlv[5];
    {
        float4 r0 = *(const float4*)(g_xr + node * 8);
        xrv[0] = r0.x; xrv[1] = r0.y; xrv[2] = r0.z; xrv[3] = r0.w;
        xrv[4] = g_xr[node * 8 + 4];
        float4 l0 = *(const float4*)(g_xl + node * 8);
        xlv[0] = l0.x; xlv[1] = l0.y; xlv[2] = l0.z; xlv[3] = l0.w;
        xlv[4] = g_xl[node * 8 + 4];
    }

    int beg = __ldg(&g_rowptr[node]), end = __ldg(&g_rowptr[node + 1]);

    float d = 0.f;
    float num[5] = {0.f, 0.f, 0.f, 0.f, 0.f};

    for (int i = beg + lane; i < end; i += 32) {
        uint4 u = __ldcs(&g_rec[i]);              // streaming: don't evict xl from L2
        int s = (int)(((u.x & 31u) << 14) | ((u.y & 31u) << 9) |
                      ((u.z & 31u) << 4) | (u.w & 15u));
        float eax = __uint_as_float(u.x), eay = __uint_as_float(u.y);
        float eaz = __uint_as_float(u.z), eaw = __uint_as_float(u.w);
        float v[5];
        float4 v0 = *(const float4*)(g_xl + s * 8);
        v[0] = v0.x; v[1] = v0.y; v[2] = v0.z; v[3] = v0.w;
        v[4] = g_xl[s * 8 + 4];
        float logit = 0.f;
#pragma unroll
        for (int j = 0; j < 5; j++) {
            float e = v[j] + xrv[j];
            e = fmaf(eax, we[0][j], e);
            e = fmaf(eay, we[1][j], e);
            e = fmaf(eaz, we[2][j], e);
            e = fmaf(eaw, we[3][j], e);
            e = (e > 0.f) ? e : 0.2f * e;
            logit = fmaf(av[j], e, logit);
        }
        float c = __expf(logit);
        d += c;
#pragma unroll
        for (int j = 0; j < 5; j++) num[j] = fmaf(c, v[j], num[j]);
    }

    // self-loop contribution (edge_attr = global mean), lane 0
    if (lane == 0) {
        float4 eav = g_eamean;
        float logit = 0.f;
#pragma unroll
        for (int j = 0; j < 5; j++) {
            float e = xlv[j] + xrv[j];
            e = fmaf(eav.x, we[0][j], e);
            e = fmaf(eav.y, we[1][j], e);
            e = fmaf(eav.z, we[2][j], e);
            e = fmaf(eav.w, we[3][j], e);
            e = (e > 0.f) ? e : 0.2f * e;
            logit = fmaf(av[j], e, logit);
        }
        float c = __expf(logit);
        d += c;
#pragma unroll
        for (int j = 0; j < 5; j++) num[j] = fmaf(c, xlv[j], num[j]);
    }

    // 6-value sum butterfly
#pragma unroll
    for (int off = 16; off > 0; off >>= 1) {
        d += __shfl_xor_sync(0xffffffffu, d, off);
#pragma unroll
        for (int j = 0; j < 5; j++) num[j] += __shfl_xor_sync(0xffffffffu, num[j], off);
    }

    if (lane == 0) {
        float inv = 1.f / d;
#pragma unroll
        for (int j = 0; j < 5; j++) {
            float h = fmaf(num[j], inv, bo[j]);
            hout[node * 5 + j] = (h > 0.f) ? h : 0.f;
        }
    }
}

// ---------------- fused mean-pool + dueling head (one block per graph) ----------------
__global__ void k_poolhead(const int* __restrict__ cur, const int* __restrict__ mask,
                           const float* __restrict__ goal,
                           const float* __restrict__ Wv1, const float* __restrict__ bv1,
                           const float* __restrict__ Wv2, const float* __restrict__ bv2,
                           const float* __restrict__ Wa1, const float* __restrict__ ba1,
                           const float* __restrict__ Wa2, const float* __restrict__ ba2,
                           float* __restrict__ out) {
    int g = blockIdx.x, tid = threadIdx.x;
    float acc[18];
#pragma unroll
    for (int f = 0; f < 18; f++) acc[f] = 0.f;
    for (int r = tid; r < NPER; r += blockDim.x) {
        int n = g * NPER + r;
#pragma unroll
        for (int j = 0; j < 5; j++) acc[j] += g_h2[n * 5 + j];
#pragma unroll
        for (int j = 0; j < 5; j++) acc[5 + j] += g_h1[n * 5 + j];
#pragma unroll
        for (int f = 0; f < 8; f++) acc[10 + f] += g_xn[n * 8 + f];
    }
#pragma unroll
    for (int off = 16; off > 0; off >>= 1)
#pragma unroll
        for (int f = 0; f < 18; f++) acc[f] += __shfl_xor_sync(0xffffffffu, acc[f], off);
    __shared__ float sm[8][18];
    int wp = tid >> 5, lane = tid & 31;
    if (lane == 0) {
#pragma unroll
        for (int f = 0; f < 18; f++) sm[wp][f] = acc[f];
    }
    __syncthreads();
    __shared__ float spool[18];
    if (tid < 18) {
        float t = 0.f;
        for (int k = 0; k < 8; k++) t += sm[k][tid];
        spool[tid] = t * (1.f / (float)NPER);
    }
    __syncthreads();

    if (tid == 0) {
        int b = g;
        int n = b * NPER + cur[b];
        float feat[42];
#pragma unroll
        for (int j = 0; j < 5; j++) feat[j] = g_h2[n * 5 + j];
#pragma unroll
        for (int j = 0; j < 5; j++) feat[5 + j] = g_h1[n * 5 + j];
#pragma unroll
        for (int f = 0; f < 8; f++) feat[10 + f] = g_xn[n * 8 + f];
#pragma unroll
        for (int k = 0; k < 18; k++) feat[18 + k] = spool[k];
#pragma unroll
        for (int k = 0; k < 6; k++) feat[36 + k] = goal[b * 6 + k];

        float hv[10], ha[10];
#pragma unroll
        for (int j = 0; j < 10; j++) { hv[j] = bv1[j]; ha[j] = ba1[j]; }
        for (int i = 0; i < 42; i++) {
            float fi = feat[i];
#pragma unroll
            for (int j = 0; j < 10; j++) {
                hv[j] = fmaf(fi, Wv1[i * 10 + j], hv[j]);
                ha[j] = fmaf(fi, Wa1[i * 10 + j], ha[j]);
            }
        }
#pragma unroll
        for (int j = 0; j < 10; j++) {
            hv[j] = (hv[j] > 0.f) ? hv[j] : 0.f;
            ha[j] = (ha[j] > 0.f) ? ha[j] : 0.f;
        }
        float val = bv2[0];
#pragma unroll
        for (int j = 0; j < 10; j++) val = fmaf(hv[j], Wv2[j], val);
        float adv[4];
#pragma unroll
        for (int k = 0; k < 4; k++) {
            adv[k] = ba2[k];
#pragma unroll
            for (int j = 0; j < 10; j++) adv[k] = fmaf(ha[j], Wa2[j * 4 + k], adv[k]);
        }
        float am = (adv[0] + adv[1] + adv[2] + adv[3]) * 0.25f;
#pragma unroll
        for (int k = 0; k < 4; k++)
            out[b * 4 + k] = (mask[b * 4 + k] == 0) ? -1e8f : (val + adv[k] - am);
    }
}

// ---------------- launch ----------------
extern "C" void kernel_launch(void* const* d_in, const int* in_sizes, int n_in,
                              void* d_out, int out_size) {
    const float* x    = (const float*)d_in[0];
    const int*   ei   = (const int*)d_in[1];
    const float* ea   = (const float*)d_in[2];
    const int*   cur  = (const int*)d_in[4];
    const int*   mask = (const int*)d_in[5];
    const float* goal = (const float*)d_in[6];
    const float* gnw  = (const float*)d_in[7];
    const float* gnb  = (const float*)d_in[8];
    const float* gnms = (const float*)d_in[9];
    const float* Wl1 = (const float*)d_in[10], *bl1 = (const float*)d_in[11];
    const float* Wr1 = (const float*)d_in[12], *br1 = (const float*)d_in[13];
    const float* We1 = (const float*)d_in[14], *att1 = (const float*)d_in[15], *bo1 = (const float*)d_in[16];
    const float* Wl2 = (const float*)d_in[17], *bl2 = (const float*)d_in[18];
    const float* Wr2 = (const float*)d_in[19], *br2 = (const float*)d_in[20];
    const float* We2 = (const float*)d_in[21], *att2 = (const float*)d_in[22], *bo2 = (const float*)d_in[23];
    const float* Wv1 = (const float*)d_in[24], *bv1 = (const float*)d_in[25];
    const float* Wv2 = (const float*)d_in[26], *bv2 = (const float*)d_in[27];
    const float* Wa1 = (const float*)d_in[28], *ba1 = (const float*)d_in[29];
    const float* Wa2 = (const float*)d_in[30], *ba2 = (const float*)d_in[31];

    const int* srcp = ei;
    const int* dstp = ei + NE;

    k_gn<<<NB, 256>>>(x, gnw, gnb, gnms, Wl1, bl1, Wr1, br1);   // 1
    k_count<<<2048, 256>>>(dstp);                               // 2
    k_scan<<<512, 1024>>>();                                    // 3
    k_scatter<<<2048, 256>>>(srcp, dstp, ea);                   // 4  <- ncu capture slot
    k_gat<1><<<NN / 8, 256>>>(We1, att1, bo1);                  // 5
    k_lr2<<<NN / 256, 256>>>(Wl2, bl2, Wr2, br2);               // 6
    k_gat<2><<<NN / 8, 256>>>(We2, att2, bo2);                  // 7
    k_poolhead<<<NB, 256>>>(cur, mask, goal, Wv1, bv1, Wv2, bv2,
                            Wa1, ba1, Wa2, ba2, (float*)d_out); // 8
}

// round 4
// speedup vs baseline: 1.7109x; 1.7109x over previous
#include <cuda_runtime.h>

#define NN   524288      // nodes
#define NE   12582912    // edges
#define NB   64          // graphs
#define NPER 8192        // nodes per graph
#define F0   8
#define HID  5

// ---------------- device scratch (static; no allocation allowed) ----------------
__device__ float  g_xn[NN * F0];       // normalized x
__device__ float  g_h1[NN * HID];      // layer-1 output
__device__ float  g_h2[NN * HID];      // layer-2 output
__device__ float  g_xl[NN * 8];        // padded 32B rows (one sector per gather)
__device__ float  g_xr[NN * 8];
__device__ float  g_acc[NN * 8];       // per-node {d, n0,n1,n2, n3,n4, -, -} (L2-resident)
__device__ int    g_ticket2;
__device__ double g_easum[4];
__device__ float4 g_eamean;

// vector reductions (fire-and-forget, no return latency)
__device__ __forceinline__ void red_v4(float* p, float a, float b, float c, float d) {
    asm volatile("red.global.add.v4.f32 [%0], {%1,%2,%3,%4};"
                 :: "l"(p), "f"(a), "f"(b), "f"(c), "f"(d) : "memory");
}
__device__ __forceinline__ void red_v2(float* p, float a, float b) {
    asm volatile("red.global.add.v2.f32 [%0], {%1,%2};"
                 :: "l"(p), "f"(a), "f"(b) : "memory");
}

// ---------------- GraphNorm + layer-1 lr + acc zero, fused (one block per graph) ----------------
__global__ void k_gn(const float* __restrict__ x, const float* __restrict__ w,
                     const float* __restrict__ b, const float* __restrict__ ms,
                     const float* __restrict__ Wl, const float* __restrict__ bl,
                     const float* __restrict__ Wr, const float* __restrict__ br) {
    int g = blockIdx.x, tid = threadIdx.x;

    // zero accumulator table + launch state (grid-stride across all blocks)
    float4 z4 = make_float4(0.f, 0.f, 0.f, 0.f);
    for (int i = g * 256 + tid; i < NN * 2; i += NB * 256)
        ((float4*)g_acc)[i] = z4;
    if (g == 0) {
        if (tid < 4) g_easum[tid] = 0.0;
        if (tid == 4) g_ticket2 = 0;
    }

    __shared__ float sWl[40], sWr[40], sbl[5], sbr[5];
    if (tid < 40) { sWl[tid] = Wl[tid]; sWr[tid] = Wr[tid]; }
    if (tid >= 40 && tid < 45) { sbl[tid - 40] = bl[tid - 40]; sbr[tid - 40] = br[tid - 40]; }

    float s1[F0], s2[F0];
#pragma unroll
    for (int f = 0; f < F0; f++) { s1[f] = 0.f; s2[f] = 0.f; }
    for (int r = tid; r < NPER; r += blockDim.x) {
        const float* row = x + (size_t)(g * NPER + r) * F0;
#pragma unroll
        for (int f = 0; f < F0; f++) { float v = row[f]; s1[f] += v; s2[f] += v * v; }
    }
#pragma unroll
    for (int off = 16; off > 0; off >>= 1)
#pragma unroll
        for (int f = 0; f < F0; f++) {
            s1[f] += __shfl_xor_sync(0xffffffffu, s1[f], off);
            s2[f] += __shfl_xor_sync(0xffffffffu, s2[f], off);
        }
    __shared__ float sm[8][2 * F0];
    int wp = tid >> 5, lane = tid & 31;
    if (lane == 0) {
#pragma unroll
        for (int f = 0; f < F0; f++) { sm[wp][f] = s1[f]; sm[wp][F0 + f] = s2[f]; }
    }
    __syncthreads();
    __shared__ float meanms[F0], scale[F0], bias[F0];
    if (tid < F0) {
        float t1 = 0.f, t2 = 0.f;
        for (int k = 0; k < 8; k++) { t1 += sm[k][tid]; t2 += sm[k][F0 + tid]; }
        float mean = t1 / (float)NPER, ex2 = t2 / (float)NPER, m = ms[tid];
        float var = ex2 - 2.f * m * mean * mean + m * m * mean * mean;
        meanms[tid] = m * mean;
        scale[tid] = w[tid] * rsqrtf(var + 1e-5f);
        bias[tid] = b[tid];
    }
    __syncthreads();
    for (int r = tid; r < NPER; r += blockDim.x) {
        int n = g * NPER + r;
        const float* row = x + (size_t)n * F0;
        float xv[F0];
        float* orow = g_xn + (size_t)n * F0;
#pragma unroll
        for (int f = 0; f < F0; f++) {
            xv[f] = scale[f] * (row[f] - meanms[f]) + bias[f];
            orow[f] = xv[f];
        }
        float l[5], rr[5];
#pragma unroll
        for (int j = 0; j < 5; j++) { l[j] = sbl[j]; rr[j] = sbr[j]; }
#pragma unroll
        for (int i = 0; i < F0; i++)
#pragma unroll
            for (int j = 0; j < 5; j++) {
                l[j] = fmaf(xv[i], sWl[i * 5 + j], l[j]);
                rr[j] = fmaf(xv[i], sWr[i * 5 + j], rr[j]);
            }
        float4* lp = (float4*)(g_xl + n * 8);
        float4* rp = (float4*)(g_xr + n * 8);
        lp[0] = make_float4(l[0], l[1], l[2], l[3]);
        lp[1] = make_float4(l[4], 0.f, 0.f, 0.f);
        rp[0] = make_float4(rr[0], rr[1], rr[2], rr[3]);
        rp[1] = make_float4(rr[4], 0.f, 0.f, 0.f);
    }
}

// ---------------- edge sweep: exp(logit) accumulated by vector red ----------------
template<int L>
__global__ void k_edge(const int* __restrict__ src, const int* __restrict__ dst,
                       const float* __restrict__ ea,
                       const float* __restrict__ We, const float* __restrict__ att) {
    float we[4][5], av[5];
#pragma unroll
    for (int k = 0; k < 4; k++)
#pragma unroll
        for (int j = 0; j < 5; j++) we[k][j] = __ldg(&We[k * 5 + j]);
#pragma unroll
    for (int j = 0; j < 5; j++) av[j] = __ldg(&att[j]);

    int stride = gridDim.x * blockDim.x;
    const int4* s4 = (const int4*)src;
    const int4* d4 = (const int4*)dst;
    const float4* e4 = (const float4*)ea;
    double a0 = 0.0, a1 = 0.0, a2 = 0.0, a3 = 0.0;

    for (int e = blockIdx.x * blockDim.x + threadIdx.x; e < NE / 4; e += stride) {
        int4 ss = __ldcs(s4 + e);
        int4 dd = __ldcs(d4 + e);
        int sl[4] = {ss.x, ss.y, ss.z, ss.w};
        int dl[4] = {dd.x, dd.y, dd.z, dd.w};
        float4 ev[4];
        ev[0] = __ldcs(e4 + (size_t)e * 4 + 0);
        ev[1] = __ldcs(e4 + (size_t)e * 4 + 1);
        ev[2] = __ldcs(e4 + (size_t)e * 4 + 2);
        ev[3] = __ldcs(e4 + (size_t)e * 4 + 3);
        if (L == 1) {
            a0 += (double)ev[0].x + ev[1].x + ev[2].x + ev[3].x;
            a1 += (double)ev[0].y + ev[1].y + ev[2].y + ev[3].y;
            a2 += (double)ev[0].z + ev[1].z + ev[2].z + ev[3].z;
            a3 += (double)ev[0].w + ev[1].w + ev[2].w + ev[3].w;
        }
#pragma unroll
        for (int q = 0; q < 4; q++) {
            int s = sl[q], d = dl[q];
            float4 v0 = *(const float4*)(g_xl + s * 8);
            float  v4v = g_xl[s * 8 + 4];
            float4 r0 = *(const float4*)(g_xr + d * 8);
            float  r4v = g_xr[d * 8 + 4];
            float vv[5] = {v0.x, v0.y, v0.z, v0.w, v4v};
            float rr[5] = {r0.x, r0.y, r0.z, r0.w, r4v};
            float logit = 0.f;
#pragma unroll
            for (int j = 0; j < 5; j++) {
                float t = vv[j] + rr[j];
                t = fmaf(ev[q].x, we[0][j], t);
                t = fmaf(ev[q].y, we[1][j], t);
                t = fmaf(ev[q].z, we[2][j], t);
                t = fmaf(ev[q].w, we[3][j], t);
                t = (t > 0.f) ? t : 0.2f * t;
                logit = fmaf(av[j], t, logit);
            }
            float c = __expf(logit);
            float* accp = g_acc + (size_t)d * 8;
            red_v4(accp, c, c * vv[0], c * vv[1], c * vv[2]);
            red_v2(accp + 4, c * vv[3], c * vv[4]);
        }
    }

    if (L == 1) {
#pragma unroll
        for (int off = 16; off > 0; off >>= 1) {
            a0 += __shfl_xor_sync(0xffffffffu, a0, off);
            a1 += __shfl_xor_sync(0xffffffffu, a1, off);
            a2 += __shfl_xor_sync(0xffffffffu, a2, off);
            a3 += __shfl_xor_sync(0xffffffffu, a3, off);
        }
        __shared__ double sd[8][4];
        int wp = threadIdx.x >> 5, lane = threadIdx.x & 31;
        if (lane == 0) { sd[wp][0] = a0; sd[wp][1] = a1; sd[wp][2] = a2; sd[wp][3] = a3; }
        __syncthreads();
        if (threadIdx.x < 4) {
            double t = 0.0;
            for (int k = 0; k < 8; k++) t += sd[k][threadIdx.x];
            atomicAdd(&g_easum[threadIdx.x], t);
        }
        __syncthreads();
        if (threadIdx.x == 0) {
            __threadfence();
            int t = atomicAdd(&g_ticket2, 1);
            if (t == (int)gridDim.x - 1) {
                __threadfence();
                double inv = 1.0 / (double)NE;
                double e0 = *((volatile double*)&g_easum[0]);
                double e1 = *((volatile double*)&g_easum[1]);
                double e2 = *((volatile double*)&g_easum[2]);
                double e3 = *((volatile double*)&g_easum[3]);
                g_eamean = make_float4((float)(e0 * inv), (float)(e1 * inv),
                                       (float)(e2 * inv), (float)(e3 * inv));
            }
        }
    }
}

// ---------------- node pass: self-loop + normalize (+ fused lr2 / acc re-zero for L1) ----------------
template<int L>
__global__ void k_node(const float* __restrict__ We, const float* __restrict__ att,
                       const float* __restrict__ bo,
                       const float* __restrict__ Wl2, const float* __restrict__ bl2,
                       const float* __restrict__ Wr2, const float* __restrict__ br2) {
    int n = blockIdx.x * blockDim.x + threadIdx.x;
    if (n >= NN) return;

    float xlv[5], xrv[5];
    {
        float4 l0 = *(const float4*)(g_xl + n * 8);
        xlv[0] = l0.x; xlv[1] = l0.y; xlv[2] = l0.z; xlv[3] = l0.w;
        xlv[4] = g_xl[n * 8 + 4];
        float4 r0 = *(const float4*)(g_xr + n * 8);
        xrv[0] = r0.x; xrv[1] = r0.y; xrv[2] = r0.z; xrv[3] = r0.w;
        xrv[4] = g_xr[n * 8 + 4];
    }

    // self-loop term (edge_attr = global mean)
    float4 eav = g_eamean;
    float logit = 0.f;
#pragma unroll
    for (int j = 0; j < 5; j++) {
        float t = xlv[j] + xrv[j];
        t = fmaf(eav.x, __ldg(&We[0 * 5 + j]), t);
        t = fmaf(eav.y, __ldg(&We[1 * 5 + j]), t);
        t = fmaf(eav.z, __ldg(&We[2 * 5 + j]), t);
        t = fmaf(eav.w, __ldg(&We[3 * 5 + j]), t);
        t = (t > 0.f) ? t : 0.2f * t;
        logit = fmaf(__ldg(&att[j]), t, logit);
    }
    float c = __expf(logit);

    float4 a0 = *(const float4*)(g_acc + (size_t)n * 8);
    float2 a1 = *(const float2*)(g_acc + (size_t)n * 8 + 4);
    float d = a0.x + c;
    float num[5] = {a0.y + c * xlv[0], a0.z + c * xlv[1], a0.w + c * xlv[2],
                    a1.x + c * xlv[3], a1.y + c * xlv[4]};
    float inv = 1.f / d;
    float h[5];
#pragma unroll
    for (int j = 0; j < 5; j++) {
        float t = fmaf(num[j], inv, __ldg(&bo[j]));
        h[j] = (t > 0.f) ? t : 0.f;
    }

    if (L == 1) {
        // store h1, re-zero accumulator, compute layer-2 xl/xr from [h1, xn]
#pragma unroll
        for (int j = 0; j < 5; j++) g_h1[n * 5 + j] = h[j];
        float4 z4 = make_float4(0.f, 0.f, 0.f, 0.f);
        ((float4*)(g_acc + (size_t)n * 8))[0] = z4;
        ((float4*)(g_acc + (size_t)n * 8))[1] = z4;

        float xv[13];
#pragma unroll
        for (int j = 0; j < 5; j++) xv[j] = h[j];
#pragma unroll
        for (int f = 0; f < 8; f++) xv[5 + f] = g_xn[n * 8 + f];
        float l[5], r[5];
#pragma unroll
        for (int j = 0; j < 5; j++) { l[j] = __ldg(&bl2[j]); r[j] = __ldg(&br2[j]); }
#pragma unroll
        for (int i = 0; i < 13; i++)
#pragma unroll
            for (int j = 0; j < 5; j++) {
                l[j] = fmaf(xv[i], __ldg(&Wl2[i * 5 + j]), l[j]);
                r[j] = fmaf(xv[i], __ldg(&Wr2[i * 5 + j]), r[j]);
            }
        float4* lp = (float4*)(g_xl + n * 8);
        float4* rp = (float4*)(g_xr + n * 8);
        lp[0] = make_float4(l[0], l[1], l[2], l[3]);
        lp[1] = make_float4(l[4], 0.f, 0.f, 0.f);
        rp[0] = make_float4(r[0], r[1], r[2], r[3]);
        rp[1] = make_float4(r[4], 0.f, 0.f, 0.f);
    } else {
#pragma unroll
        for (int j = 0; j < 5; j++) g_h2[n * 5 + j] = h[j];
    }
}

// ---------------- fused mean-pool + dueling head (one block per graph) ----------------
__global__ void k_poolhead(const int* __restrict__ cur, const int* __restrict__ mask,
                           const float* __restrict__ goal,
                           const float* __restrict__ Wv1, const float* __restrict__ bv1,
                           const float* __restrict__ Wv2, const float* __restrict__ bv2,
                           const float* __restrict__ Wa1, const float* __restrict__ ba1,
                           const float* __restrict__ Wa2, const float* __restrict__ ba2,
                           float* __restrict__ out) {
    int g = blockIdx.x, tid = threadIdx.x;
    float acc[18];
#pragma unroll
    for (int f = 0; f < 18; f++) acc[f] = 0.f;
    for (int r = tid; r < NPER; r += blockDim.x) {
        int n = g * NPER + r;
#pragma unroll
        for (int j = 0; j < 5; j++) acc[j] += g_h2[n * 5 + j];
#pragma unroll
        for (int j = 0; j < 5; j++) acc[5 + j] += g_h1[n * 5 + j];
#pragma unroll
        for (int f = 0; f < 8; f++) acc[10 + f] += g_xn[n * 8 + f];
    }
#pragma unroll
    for (int off = 16; off > 0; off >>= 1)
#pragma unroll
        for (int f = 0; f < 18; f++) acc[f] += __shfl_xor_sync(0xffffffffu, acc[f], off);
    __shared__ float sm[8][18];
    int wp = tid >> 5, lane = tid & 31;
    if (lane == 0) {
#pragma unroll
        for (int f = 0; f < 18; f++) sm[wp][f] = acc[f];
    }
    __syncthreads();
    __shared__ float spool[18];
    if (tid < 18) {
        float t = 0.f;
        for (int k = 0; k < 8; k++) t += sm[k][tid];
        spool[tid] = t * (1.f / (float)NPER);
    }
    __syncthreads();

    if (tid == 0) {
        int b = g;
        int n = b * NPER + cur[b];
        float feat[42];
#pragma unroll
        for (int j = 0; j < 5; j++) feat[j] = g_h2[n * 5 + j];
#pragma unroll
        for (int j = 0; j < 5; j++) feat[5 + j] = g_h1[n * 5 + j];
#pragma unroll
        for (int f = 0; f < 8; f++) feat[10 + f] = g_xn[n * 8 + f];
#pragma unroll
        for (int k = 0; k < 18; k++) feat[18 + k] = spool[k];
#pragma unroll
        for (int k = 0; k < 6; k++) feat[36 + k] = goal[b * 6 + k];

        float hv[10], ha[10];
#pragma unroll
        for (int j = 0; j < 10; j++) { hv[j] = bv1[j]; ha[j] = ba1[j]; }
        for (int i = 0; i < 42; i++) {
            float fi = feat[i];
#pragma unroll
            for (int j = 0; j < 10; j++) {
                hv[j] = fmaf(fi, Wv1[i * 10 + j], hv[j]);
                ha[j] = fmaf(fi, Wa1[i * 10 + j], ha[j]);
            }
        }
#pragma unroll
        for (int j = 0; j < 10; j++) {
            hv[j] = (hv[j] > 0.f) ? hv[j] : 0.f;
            ha[j] = (ha[j] > 0.f) ? ha[j] : 0.f;
        }
        float val = bv2[0];
#pragma unroll
        for (int j = 0; j < 10; j++) val = fmaf(hv[j], Wv2[j], val);
        float adv[4];
#pragma unroll
        for (int k = 0; k < 4; k++) {
            adv[k] = ba2[k];
#pragma unroll
            for (int j = 0; j < 10; j++) adv[k] = fmaf(ha[j], Wa2[j * 4 + k], adv[k]);
        }
        float am = (adv[0] + adv[1] + adv[2] + adv[3]) * 0.25f;
#pragma unroll
        for (int k = 0; k < 4; k++)
            out[b * 4 + k] = (mask[b * 4 + k] == 0) ? -1e8f : (val + adv[k] - am);
    }
}

// ---------------- launch ----------------
extern "C" void kernel_launch(void* const* d_in, const int* in_sizes, int n_in,
                              void* d_out, int out_size) {
    const float* x    = (const float*)d_in[0];
    const int*   ei   = (const int*)d_in[1];
    const float* ea   = (const float*)d_in[2];
    const int*   cur  = (const int*)d_in[4];
    const int*   mask = (const int*)d_in[5];
    const float* goal = (const float*)d_in[6];
    const float* gnw  = (const float*)d_in[7];
    const float* gnb  = (const float*)d_in[8];
    const float* gnms = (const float*)d_in[9];
    const float* Wl1 = (const float*)d_in[10], *bl1 = (const float*)d_in[11];
    const float* Wr1 = (const float*)d_in[12], *br1 = (const float*)d_in[13];
    const float* We1 = (const float*)d_in[14], *att1 = (const float*)d_in[15], *bo1 = (const float*)d_in[16];
    const float* Wl2 = (const float*)d_in[17], *bl2 = (const float*)d_in[18];
    const float* Wr2 = (const float*)d_in[19], *br2 = (const float*)d_in[20];
    const float* We2 = (const float*)d_in[21], *att2 = (const float*)d_in[22], *bo2 = (const float*)d_in[23];
    const float* Wv1 = (const float*)d_in[24], *bv1 = (const float*)d_in[25];
    const float* Wv2 = (const float*)d_in[26], *bv2 = (const float*)d_in[27];
    const float* Wa1 = (const float*)d_in[28], *ba1 = (const float*)d_in[29];
    const float* Wa2 = (const float*)d_in[30], *ba2 = (const float*)d_in[31];

    const int* srcp = ei;
    const int* dstp = ei + NE;

    k_gn<<<NB, 256>>>(x, gnw, gnb, gnms, Wl1, bl1, Wr1, br1);       // 1
    k_edge<1><<<2048, 256>>>(srcp, dstp, ea, We1, att1);            // 2
    k_node<1><<<NN / 256, 256>>>(We1, att1, bo1, Wl2, bl2, Wr2, br2);// 3
    k_edge<2><<<2048, 256>>>(srcp, dstp, ea, We2, att2);            // 4  <- ncu capture slot
    k_node<2><<<NN / 256, 256>>>(We2, att2, bo2, 0, 0, 0, 0);       // 5
    k_poolhead<<<NB, 256>>>(cur, mask, goal, Wv1, bv1, Wv2, bv2,
                            Wa1, ba1, Wa2, ba2, (float*)d_out);     // 6
}